// round 10
// baseline (speedup 1.0000x reference)
#include <cuda_runtime.h>
#include <cuda_fp16.h>
#include <cstdint>

// ---------------------------------------------------------------------------
// BenesBlock via mma.sync (HMMA), single-pass fp16 GEMMs.
// Residual exact fp32 (g_y32); fp16 shadow feeds GEMM1. h fp16 end-to-end.
// Column stats finalized INSIDE gemm1 via per-strip arrival counters
// (no stats_final launch). 2-stage cp.async double buffer (R7-proven).
// ---------------------------------------------------------------------------

#define L    8192
#define NU   512
#define M_   4096
#define K1   1024
#define N1   2048
#define K2   2048
#define N2   1024
#define CW_F 0.10897247358851683f
#define EPS_F 1e-6f

#define STAGE 32768                 // A16K | B16K
#define SMEM_DYN (2 * STAGE)        // 64KB double buffered -> 2 CTAs/SM

// ---------------------------------------------------------------------------
__device__ __align__(16) float  g_y32[2][L * NU];         // exact residual
__device__ __align__(16) __half g_y16[2][L * NU];         // GEMM1 A operand
__device__ __align__(16) __half g_h2[M_ * N1];            // h fp16 -> LN'd in place
__device__ __align__(16) __half g_w1t[3][N1 * K1];        // [stage][N,K] fp16
__device__ __align__(16) __half g_w2t[3][N2 * K2];
__device__ float g_part[32][2 * N1];
__device__ float g_stats[2 * N1];
__device__ float g_sig[3 * NU];
__device__ int   g_cnt[16];                               // per-n-strip arrival

// ---------------------------------------------------------------------------
__device__ __forceinline__ uint32_t smem_u32(const void* p) {
    uint32_t a;
    asm("{ .reg .u64 t; cvta.to.shared.u64 t, %1; cvt.u32.u64 %0, t; }" : "=r"(a) : "l"(p));
    return a;
}
__device__ __forceinline__ uint32_t sw128(uint32_t off) { return off ^ ((off >> 3) & 0x70); }

#define CP16(s, g) asm volatile("cp.async.cg.shared.global [%0], [%1], 16;" :: "r"(s), "l"(g))
#define CP_COMMIT() asm volatile("cp.async.commit_group;" ::: "memory")

#define LDSM4(r0, r1, r2, r3, addr)                                              \
    asm volatile("ldmatrix.sync.aligned.m8n8.x4.shared.b16 {%0,%1,%2,%3}, [%4];" \
                 : "=r"(r0), "=r"(r1), "=r"(r2), "=r"(r3) : "r"(addr))

#define MMA(acc, a, b0, b1)                                                      \
    asm volatile("mma.sync.aligned.m16n8k16.row.col.f32.f16.f16.f32 "            \
                 "{%0,%1,%2,%3}, {%4,%5,%6,%7}, {%8,%9}, {%0,%1,%2,%3};"         \
                 : "+f"((acc)[0]), "+f"((acc)[1]), "+f"((acc)[2]), "+f"((acc)[3])\
                 : "r"((a)[0]), "r"((a)[1]), "r"((a)[2]), "r"((a)[3]),           \
                   "r"(b0), "r"(b1))

// ---------------------------------------------------------------------------
__global__ void copy_x_kernel(const float* __restrict__ x,
                              const float* __restrict__ rs_f,
                              const float* __restrict__ rs_r,
                              const float* __restrict__ rs_m) {
    if (blockIdx.x == (L * NU) / 256) {
        for (int i = threadIdx.x; i < 3 * NU; i += 256) {
            const float* src = (i < NU) ? rs_f : (i < 2 * NU) ? rs_r : rs_m;
            float v = src[i & (NU - 1)];
            g_sig[i] = 1.0f / (1.0f + expf(-v));
        }
        if (blockIdx.x == (L * NU) / 256 && threadIdx.x < 16) g_cnt[threadIdx.x] = 0;
        return;
    }
    int i = blockIdx.x * 256 + threadIdx.x;
    float v = x[i];
    g_y32[0][i] = v;
    g_y16[0][i] = __float2half_rn(v);
}

// All 6 weight transposes in one launch. z: stage = z>>1, which = z&1.
__global__ void transpose_half_all(const float* __restrict__ w1f, const float* __restrict__ w2f,
                                   const float* __restrict__ w1r, const float* __restrict__ w2r,
                                   const float* __restrict__ w1m, const float* __restrict__ w2m) {
    __shared__ float t[32][33];
    int stage = blockIdx.z >> 1;
    int which = blockIdx.z & 1;
    int R = which ? K2 : K1;
    int C = which ? N2 : N1;
    if ((int)blockIdx.x * 32 >= C || (int)blockIdx.y * 32 >= R) return;
    const float* w = which ? (stage == 0 ? w2f : stage == 1 ? w2r : w2m)
                           : (stage == 0 ? w1f : stage == 1 ? w1r : w1m);
    __half* o = which ? g_w2t[stage] : g_w1t[stage];
    int c0 = blockIdx.x * 32, r0 = blockIdx.y * 32;
    for (int j = threadIdx.y; j < 32; j += 8)
        t[j][threadIdx.x] = w[(size_t)(r0 + j) * C + c0 + threadIdx.x];
    __syncthreads();
    for (int j = threadIdx.y; j < 32; j += 8) {
        float v = t[threadIdx.x][j];
        o[(size_t)(c0 + j) * R + r0 + threadIdx.x] = __float2half_rn(v);
    }
}

// In-place LN + leaky-relu on fp16 h. grid 4096, block 256, 8 halves/thread.
__global__ void prep2_kernel() {
    int i = blockIdx.x * 256 + threadIdx.x;
    uint4 v = ((const uint4*)g_h2)[i];
    int col = (i * 8) & (N1 - 1);
    __half2* hp = (__half2*)&v;
    uint4 outv;
    __half2* op = (__half2*)&outv;
#pragma unroll
    for (int j = 0; j < 4; j++) {
        float2 xv = __half22float2(hp[j]);
        float4 st = *(const float4*)&g_stats[2 * (col + 2 * j)];
        float a = (xv.x - st.x) * st.y;
        float b = (xv.y - st.z) * st.w;
        a = a > 0.f ? a : 0.2f * a;
        b = b > 0.f ? b : 0.2f * b;
        op[j] = __floats2half2_rn(a, b);
    }
    ((uint4*)g_h2)[i] = outv;
}

// ---------------------------------------------------------------------------
// Stage: A 16K | B 16K. 8 cp.async per thread.
__device__ __forceinline__ void load_stage(uint32_t sb, int s, int ck,
                                           const __half* A, const __half* B,
                                           int Kt, int m0, int n0) {
    int tid = threadIdx.x;
    int r = tid >> 1;
    int c0 = (tid & 1) * 4;
    uint32_t base = sb + s * STAGE;
    size_t rs = (size_t)Kt * 2;
    size_t kb = (size_t)ck * 128;
    const char* pA = (const char*)A + (size_t)(m0 + r) * rs + kb;
    const char* pB = (const char*)B + (size_t)(n0 + r) * rs + kb;
#pragma unroll
    for (int c = 0; c < 4; c++) {
        int ch = c0 + c;
        uint32_t so = sw128((uint32_t)(r * 128 + ch * 16));
        CP16(base + so,         pA + ch * 16);
        CP16(base + 16384 + so, pB + ch * 16);
    }
    CP_COMMIT();
}

__device__ __forceinline__ void compute_chunk(uint32_t base, int lane, int wm, int wn,
                                              float acc[2][8][4]) {
#pragma unroll
    for (int k16 = 0; k16 < 4; k16++) {
        uint32_t koff = k16 * 32 + (lane >> 4) * 16;
        uint32_t ah[2][4];
#pragma unroll
        for (int mt = 0; mt < 2; mt++) {
            int row = wm * 32 + mt * 16 + (lane & 15);
            uint32_t off = sw128((uint32_t)(row * 128) + koff);
            LDSM4(ah[mt][0], ah[mt][1], ah[mt][2], ah[mt][3], base + off);
        }
        uint32_t bh[8][2];
#pragma unroll
        for (int g = 0; g < 4; g++) {
            int row = wn * 64 + g * 16 + (lane & 15);
            uint32_t off = sw128((uint32_t)(row * 128) + koff);
            uint32_t q0, q1, q2, q3;
            LDSM4(q0, q1, q2, q3, base + 16384 + off);
            bh[2 * g][0] = q0; bh[2 * g][1] = q2;
            bh[2 * g + 1][0] = q1; bh[2 * g + 1][1] = q3;
        }
#pragma unroll
        for (int mt = 0; mt < 2; mt++)
#pragma unroll
            for (int nt = 0; nt < 8; nt++)
                MMA(acc[mt][nt], ah[mt], bh[nt][0], bh[nt][1]);
    }
}

// R7-proven 2-stage double buffer.
__device__ __forceinline__ void gemm_main(uint32_t sb,
                                          const __half* A, const __half* B,
                                          int Kt, int m0, int n0, float acc[2][8][4]) {
#pragma unroll
    for (int i = 0; i < 2; i++)
#pragma unroll
        for (int j = 0; j < 8; j++)
#pragma unroll
            for (int q = 0; q < 4; q++) acc[i][j][q] = 0.f;

    const int NK = Kt >> 6;
    const int lane = threadIdx.x & 31, wid = threadIdx.x >> 5;
    const int wm = wid & 3, wn = wid >> 2;

    load_stage(sb, 0, 0, A, B, Kt, m0, n0);
    for (int ck = 0; ck < NK; ck++) {
        if (ck + 1 < NK) {
            load_stage(sb, (ck + 1) & 1, ck + 1, A, B, Kt, m0, n0);
            asm volatile("cp.async.wait_group 1;" ::: "memory");
        } else {
            asm volatile("cp.async.wait_group 0;" ::: "memory");
        }
        __syncthreads();
        compute_chunk(sb + (ck & 1) * STAGE, lane, wm, wn, acc);
        __syncthreads();
    }
}

// ---------------------------------------------------------------------------
// GEMM1: h(fp16) = y16 @ w1t^T + fused per-CTA stats partials + in-kernel
// finalize (last CTA per n-strip computes mean/rstd for its 128 columns).
__global__ __launch_bounds__(256, 2) void gemm1_mma(int cur, int stage) {
    extern __shared__ char smem[];
    uint32_t sb = smem_u32(smem);
    int m0 = blockIdx.y * 128, n0 = blockIdx.x * 128;
    float acc[2][8][4];
    gemm_main(sb, g_y16[cur], g_w1t[stage], K1, m0, n0, acc);

    int lane = threadIdx.x & 31, wid = threadIdx.x >> 5;
    int wm = wid & 3, wn = wid >> 2;
#pragma unroll
    for (int mt = 0; mt < 2; mt++) {
        int r0 = m0 + wm * 32 + mt * 16 + (lane >> 2);
#pragma unroll
        for (int nt = 0; nt < 8; nt++) {
            int cc = n0 + wn * 64 + nt * 8 + (lane & 3) * 2;
            *(__half2*)&g_h2[(size_t)r0 * N1 + cc] =
                __floats2half2_rn(acc[mt][nt][0], acc[mt][nt][1]);
            *(__half2*)&g_h2[(size_t)(r0 + 8) * N1 + cc] =
                __floats2half2_rn(acc[mt][nt][2], acc[mt][nt][3]);
        }
    }

    // per-CTA column stats over this CTA's 128 rows (from exact fp32 acc)
    float s[8][2], q[8][2];
#pragma unroll
    for (int nt = 0; nt < 8; nt++)
#pragma unroll
        for (int p = 0; p < 2; p++) {
            float a0 = acc[0][nt][p], a1 = acc[0][nt][2 + p];
            float a2 = acc[1][nt][p], a3 = acc[1][nt][2 + p];
            s[nt][p] = a0 + a1 + a2 + a3;
            q[nt][p] = a0 * a0 + a1 * a1 + a2 * a2 + a3 * a3;
        }
#pragma unroll
    for (int off = 4; off < 32; off <<= 1)
#pragma unroll
        for (int nt = 0; nt < 8; nt++)
#pragma unroll
            for (int p = 0; p < 2; p++) {
                s[nt][p] += __shfl_xor_sync(0xffffffffu, s[nt][p], off);
                q[nt][p] += __shfl_xor_sync(0xffffffffu, q[nt][p], off);
            }
    float* red = (float*)smem;             // 4KB scratch (post-gemm smem reuse)
    if (lane < 4) {
#pragma unroll
        for (int nt = 0; nt < 8; nt++)
#pragma unroll
            for (int p = 0; p < 2; p++) {
                int cl = wn * 64 + nt * 8 + lane * 2 + p;
                red[(wm * 128 + cl) * 2 + 0] = s[nt][p];
                red[(wm * 128 + cl) * 2 + 1] = q[nt][p];
            }
    }
    __syncthreads();
    if (threadIdx.x < 128) {
        int cl = threadIdx.x;
        float S = red[cl * 2]           + red[(128 + cl) * 2] +
                  red[(256 + cl) * 2]   + red[(384 + cl) * 2];
        float Q = red[cl * 2 + 1]         + red[(128 + cl) * 2 + 1] +
                  red[(256 + cl) * 2 + 1] + red[(384 + cl) * 2 + 1];
        g_part[blockIdx.y][2 * (n0 + cl)]     = S;
        g_part[blockIdx.y][2 * (n0 + cl) + 1] = Q;
    }

    // arrival counter: last CTA of this n-strip finalizes stats.
    __shared__ int is_last;
    __threadfence();
    __syncthreads();
    if (threadIdx.x == 0) {
        int old = atomicAdd(&g_cnt[blockIdx.x], 1);
        is_last = (old == 31) ? 1 : 0;
    }
    __syncthreads();
    if (is_last) {
        __threadfence();
        if (threadIdx.x < 128) {
            int c = n0 + threadIdx.x;
            float Sf = 0.f, Qf = 0.f;
#pragma unroll
            for (int rg = 0; rg < 32; rg++) {
                Sf += g_part[rg][2 * c];
                Qf += g_part[rg][2 * c + 1];
            }
            float mean = Sf * (1.0f / M_);
            float var = Qf * (1.0f / M_) - mean * mean;
            g_stats[2 * c] = mean;
            g_stats[2 * c + 1] = rsqrtf(var + EPS_F);
        }
        __syncthreads();
        if (threadIdx.x == 0) g_cnt[blockIdx.x] = 0;   // reset for next step
    }
}

// ---------------------------------------------------------------------------
// GEMM2: cand = h2 @ w2t^T; epilogue: +b2, fp32 residual, Benes scatter.
__global__ __launch_bounds__(256, 2) void gemm2_mma(int stage, int dir, int cur,
                                                    const float* __restrict__ b2,
                                                    float* __restrict__ dext) {
    extern __shared__ char smem[];
    uint32_t sb = smem_u32(smem);
    int m0 = blockIdx.y * 128, n0 = blockIdx.x * 128;
    float acc[2][8][4];
    gemm_main(sb, g_h2, g_w2t[stage], K2, m0, n0, acc);

    int lane = threadIdx.x & 31, wid = threadIdx.x >> 5;
    int wm = wid & 3, wn = wid >> 2;
    const float* y = g_y32[cur];
    float* oy = g_y32[cur ^ 1];
    __half* o16 = g_y16[cur ^ 1];

#pragma unroll
    for (int mt = 0; mt < 2; mt++) {
        int rbase = m0 + wm * 32 + mt * 16 + (lane >> 2);
#pragma unroll
        for (int nt = 0; nt < 8; nt++) {
            int n = n0 + wn * 64 + nt * 8 + (lane & 3) * 2;
            int c = n & (NU - 1);
            int b = n >> 9;
            float2 bias = *(const float2*)&b2[n];
            float sig0 = g_sig[stage * NU + c];
            float sig1 = g_sig[stage * NU + c + 1];
#pragma unroll
            for (int hf = 0; hf < 2; hf++) {
                int r = rbase + hf * 8;
                int rowY = 2 * r + b;
                float cand0 = acc[mt][nt][hf * 2 + 0] + bias.x;
                float cand1 = acc[mt][nt][hf * 2 + 1] + bias.y;
                float2 yv = *(const float2*)&y[(size_t)rowY * NU + c];
                float v0 = sig0 * yv.x + cand0 * CW_F;
                float v1 = sig1 * yv.y + cand1 * CW_F;
                int dst;
                if (dir == 0)      dst = (rowY < M_) ? (2 * rowY) : (2 * rowY - L + 1);
                else if (dir == 1) dst = (rowY & 1) ? (M_ + (rowY >> 1)) : (rowY >> 1);
                else               dst = rowY;
                if (dext) {
                    *(float2*)&dext[(size_t)dst * NU + c] = make_float2(v0, v1);
                } else {
                    *(float2*)&oy[(size_t)dst * NU + c] = make_float2(v0, v1);
                    *(__half2*)&o16[(size_t)dst * NU + c] =
                        __halves2half2(__float2half_rn(v0), __float2half_rn(v1));
                }
            }
        }
    }
}

// ---------------------------------------------------------------------------
extern "C" void kernel_launch(void* const* d_in, const int* in_sizes, int n_in,
                              void* d_out, int out_size) {
    const float* x = (const float*)d_in[0];
    const float* rs[3] = {(const float*)d_in[1], (const float*)d_in[5], (const float*)d_in[9]};
    const float* w1[3] = {(const float*)d_in[2], (const float*)d_in[6], (const float*)d_in[10]};
    const float* w2[3] = {(const float*)d_in[3], (const float*)d_in[7], (const float*)d_in[11]};
    const float* b2[3] = {(const float*)d_in[4], (const float*)d_in[8], (const float*)d_in[12]};
    float* out = (float*)d_out;

    cudaFuncSetAttribute(gemm1_mma, cudaFuncAttributeMaxDynamicSharedMemorySize, SMEM_DYN);
    cudaFuncSetAttribute(gemm2_mma, cudaFuncAttributeMaxDynamicSharedMemorySize, SMEM_DYN);

    copy_x_kernel<<<(L * NU) / 256 + 1, 256>>>(x, rs[0], rs[1], rs[2]);
    transpose_half_all<<<dim3(64, 64, 6), dim3(32, 8)>>>(w1[0], w2[0], w1[1], w2[1], w1[2], w2[2]);

    dim3 g1(N1 / 128, M_ / 128);   // (16, 32)
    dim3 g2(N2 / 128, M_ / 128);   // (8, 32)

    int cur = 0;
    for (int step = 0; step < 25; step++) {
        int stage = (step < 12) ? 0 : (step < 24) ? 1 : 2;
        int dir = stage;
        gemm1_mma<<<g1, 256, SMEM_DYN>>>(cur, stage);
        prep2_kernel<<<4096, 256>>>();
        gemm2_mma<<<g2, 256, SMEM_DYN>>>(stage, dir, cur, b2[stage],
                                         (step == 24) ? out : nullptr);
        cur ^= 1;
    }
}

// round 11
// speedup vs baseline: 1.0123x; 1.0123x over previous
#include <cuda_runtime.h>
#include <cuda_fp16.h>
#include <cstdint>

// ---------------------------------------------------------------------------
// BenesBlock via mma.sync (HMMA), single-pass fp16 GEMMs.
// Residual exact fp32 (g_y32); fp16 shadow feeds GEMM1. h stored fp16 raw.
// LN + leaky-relu FUSED into gemm2's A-loader (no prep2 kernel).
// Per step: gemm1 (+fused stats partials) -> stats_final (tiny) -> gemm2.
// ---------------------------------------------------------------------------

#define L    8192
#define NU   512
#define M_   4096
#define K1   1024
#define N1   2048
#define K2   2048
#define N2   1024
#define CW_F 0.10897247358851683f
#define EPS_F 1e-6f

#define STAGE 32768                       // A16K | B16K
#define SMEM_DYN (2 * STAGE + 16384)      // + stats cache (gemm2); 80KB -> 2 CTAs/SM

// ---------------------------------------------------------------------------
__device__ __align__(16) float  g_y32[2][L * NU];         // exact residual
__device__ __align__(16) __half g_y16[2][L * NU];         // GEMM1 A operand
__device__ __align__(16) __half g_h2[M_ * N1];            // raw h (fp16)
__device__ __align__(16) __half g_w1t[3][N1 * K1];        // [stage][N,K] fp16
__device__ __align__(16) __half g_w2t[3][N2 * K2];
__device__ float g_part[32][2 * N1];
__device__ float g_stats[2 * N1];
__device__ float g_sig[3 * NU];

// ---------------------------------------------------------------------------
__device__ __forceinline__ uint32_t smem_u32(const void* p) {
    uint32_t a;
    asm("{ .reg .u64 t; cvta.to.shared.u64 t, %1; cvt.u32.u64 %0, t; }" : "=r"(a) : "l"(p));
    return a;
}
__device__ __forceinline__ uint32_t sw128(uint32_t off) { return off ^ ((off >> 3) & 0x70); }

#define CP16(s, g) asm volatile("cp.async.cg.shared.global [%0], [%1], 16;" :: "r"(s), "l"(g))
#define CP_COMMIT() asm volatile("cp.async.commit_group;" ::: "memory")

#define LDSM4(r0, r1, r2, r3, addr)                                              \
    asm volatile("ldmatrix.sync.aligned.m8n8.x4.shared.b16 {%0,%1,%2,%3}, [%4];" \
                 : "=r"(r0), "=r"(r1), "=r"(r2), "=r"(r3) : "r"(addr))

#define MMA(acc, a, b0, b1)                                                      \
    asm volatile("mma.sync.aligned.m16n8k16.row.col.f32.f16.f16.f32 "            \
                 "{%0,%1,%2,%3}, {%4,%5,%6,%7}, {%8,%9}, {%0,%1,%2,%3};"         \
                 : "+f"((acc)[0]), "+f"((acc)[1]), "+f"((acc)[2]), "+f"((acc)[3])\
                 : "r"((a)[0]), "r"((a)[1]), "r"((a)[2]), "r"((a)[3]),           \
                   "r"(b0), "r"(b1))

// ---------------------------------------------------------------------------
__global__ void copy_x_kernel(const float* __restrict__ x,
                              const float* __restrict__ rs_f,
                              const float* __restrict__ rs_r,
                              const float* __restrict__ rs_m) {
    if (blockIdx.x == (L * NU) / 256) {
        for (int i = threadIdx.x; i < 3 * NU; i += 256) {
            const float* src = (i < NU) ? rs_f : (i < 2 * NU) ? rs_r : rs_m;
            float v = src[i & (NU - 1)];
            g_sig[i] = 1.0f / (1.0f + expf(-v));
        }
        return;
    }
    int i = blockIdx.x * 256 + threadIdx.x;
    float v = x[i];
    g_y32[0][i] = v;
    g_y16[0][i] = __float2half_rn(v);
}

// All 6 weight transposes in one launch. z: stage = z>>1, which = z&1.
__global__ void transpose_half_all(const float* __restrict__ w1f, const float* __restrict__ w2f,
                                   const float* __restrict__ w1r, const float* __restrict__ w2r,
                                   const float* __restrict__ w1m, const float* __restrict__ w2m) {
    __shared__ float t[32][33];
    int stage = blockIdx.z >> 1;
    int which = blockIdx.z & 1;
    int R = which ? K2 : K1;
    int C = which ? N2 : N1;
    if ((int)blockIdx.x * 32 >= C || (int)blockIdx.y * 32 >= R) return;
    const float* w = which ? (stage == 0 ? w2f : stage == 1 ? w2r : w2m)
                           : (stage == 0 ? w1f : stage == 1 ? w1r : w1m);
    __half* o = which ? g_w2t[stage] : g_w1t[stage];
    int c0 = blockIdx.x * 32, r0 = blockIdx.y * 32;
    for (int j = threadIdx.y; j < 32; j += 8)
        t[j][threadIdx.x] = w[(size_t)(r0 + j) * C + c0 + threadIdx.x];
    __syncthreads();
    for (int j = threadIdx.y; j < 32; j += 8) {
        float v = t[threadIdx.x][j];
        o[(size_t)(c0 + j) * R + r0 + threadIdx.x] = __float2half_rn(v);
    }
}

// ---------------------------------------------------------------------------
__global__ void stats_final_kernel() {     // grid 8, block 256
    int c = blockIdx.x * 256 + threadIdx.x;
    float s = 0.f, q = 0.f;
#pragma unroll
    for (int rg = 0; rg < 32; rg++) { s += g_part[rg][2 * c]; q += g_part[rg][2 * c + 1]; }
    float mean = s * (1.0f / M_);
    float var = q * (1.0f / M_) - mean * mean;
    g_stats[2 * c] = mean;
    g_stats[2 * c + 1] = rsqrtf(var + EPS_F);
}

// ---------------------------------------------------------------------------
// Plain stage loader (gemm1): A and B both via cp.async.
__device__ __forceinline__ void load_stage(uint32_t sb, int s, int ck,
                                           const __half* A, const __half* B,
                                           int Kt, int m0, int n0) {
    int tid = threadIdx.x;
    int r = tid >> 1;
    int c0 = (tid & 1) * 4;
    uint32_t base = sb + s * STAGE;
    size_t rs = (size_t)Kt * 2;
    size_t kb = (size_t)ck * 128;
    const char* pA = (const char*)A + (size_t)(m0 + r) * rs + kb;
    const char* pB = (const char*)B + (size_t)(n0 + r) * rs + kb;
#pragma unroll
    for (int c = 0; c < 4; c++) {
        int ch = c0 + c;
        uint32_t so = sw128((uint32_t)(r * 128 + ch * 16));
        CP16(base + so,         pA + ch * 16);
        CP16(base + 16384 + so, pB + ch * 16);
    }
    CP_COMMIT();
}

// gemm2 stage loader: B via cp.async; A = raw h via LDG, LN+lrelu applied
// in registers (stats from smem cache), stored fp16 via STS.
__device__ __forceinline__ void load_stage_ln(uint32_t sb, char* smc, int s, int ck,
                                              const __half* A, const __half* B,
                                              int m0, int n0, const float* ss) {
    int tid = threadIdx.x;
    int r = tid >> 1;
    int c0 = (tid & 1) * 4;
    uint32_t base = sb + s * STAGE;
    char* cbase = smc + s * STAGE;
    size_t rs = (size_t)K2 * 2;
    size_t kb = (size_t)ck * 128;
    const char* pB = (const char*)B + (size_t)(n0 + r) * rs + kb;
#pragma unroll
    for (int c = 0; c < 4; c++) {
        int ch = c0 + c;
        uint32_t so = sw128((uint32_t)(r * 128 + ch * 16));
        CP16(base + 16384 + so, pB + ch * 16);
    }
    CP_COMMIT();
    const char* pA = (const char*)A + (size_t)(m0 + r) * rs + kb;
#pragma unroll
    for (int c = 0; c < 4; c++) {
        int ch = c0 + c;
        uint4 v = *(const uint4*)(pA + ch * 16);
        __half2* hp = (__half2*)&v;
        int k0 = ck * 64 + ch * 8;
        uint4 ov;
        __half2* op = (__half2*)&ov;
#pragma unroll
        for (int j = 0; j < 4; j++) {
            float2 xv = __half22float2(hp[j]);
            float4 st = *(const float4*)&ss[2 * (k0 + 2 * j)];
            float a = (xv.x - st.x) * st.y;
            float b = (xv.y - st.z) * st.w;
            a = a > 0.f ? a : 0.2f * a;
            b = b > 0.f ? b : 0.2f * b;
            op[j] = __floats2half2_rn(a, b);
        }
        *(uint4*)(cbase + sw128((uint32_t)(r * 128 + ch * 16))) = ov;
    }
}

__device__ __forceinline__ void compute_chunk(uint32_t base, int lane, int wm, int wn,
                                              float acc[2][8][4]) {
#pragma unroll
    for (int k16 = 0; k16 < 4; k16++) {
        uint32_t koff = k16 * 32 + (lane >> 4) * 16;
        uint32_t ah[2][4];
#pragma unroll
        for (int mt = 0; mt < 2; mt++) {
            int row = wm * 32 + mt * 16 + (lane & 15);
            uint32_t off = sw128((uint32_t)(row * 128) + koff);
            LDSM4(ah[mt][0], ah[mt][1], ah[mt][2], ah[mt][3], base + off);
        }
        uint32_t bh[8][2];
#pragma unroll
        for (int g = 0; g < 4; g++) {
            int row = wn * 64 + g * 16 + (lane & 15);
            uint32_t off = sw128((uint32_t)(row * 128) + koff);
            uint32_t q0, q1, q2, q3;
            LDSM4(q0, q1, q2, q3, base + 16384 + off);
            bh[2 * g][0] = q0; bh[2 * g][1] = q2;
            bh[2 * g + 1][0] = q1; bh[2 * g + 1][1] = q3;
        }
#pragma unroll
        for (int mt = 0; mt < 2; mt++)
#pragma unroll
            for (int nt = 0; nt < 8; nt++)
                MMA(acc[mt][nt], ah[mt], bh[nt][0], bh[nt][1]);
    }
}

// ---------------------------------------------------------------------------
// GEMM1: h(fp16 raw) = y16 @ w1t^T + fused per-CTA stats partials.
__global__ __launch_bounds__(256, 2) void gemm1_mma(int cur, int stage) {
    extern __shared__ char smem[];
    uint32_t sb = smem_u32(smem);
    int m0 = blockIdx.y * 128, n0 = blockIdx.x * 128;
    float acc[2][8][4];
#pragma unroll
    for (int i = 0; i < 2; i++)
#pragma unroll
        for (int j = 0; j < 8; j++)
#pragma unroll
            for (int q = 0; q < 4; q++) acc[i][j][q] = 0.f;

    const int lane = threadIdx.x & 31, wid = threadIdx.x >> 5;
    const int wm = wid & 3, wn = wid >> 2;
    const __half* A = g_y16[cur];
    const __half* B = g_w1t[stage];

    load_stage(sb, 0, 0, A, B, K1, m0, n0);
    for (int ck = 0; ck < (K1 >> 6); ck++) {
        if (ck + 1 < (K1 >> 6)) {
            load_stage(sb, (ck + 1) & 1, ck + 1, A, B, K1, m0, n0);
            asm volatile("cp.async.wait_group 1;" ::: "memory");
        } else {
            asm volatile("cp.async.wait_group 0;" ::: "memory");
        }
        __syncthreads();
        compute_chunk(sb + (ck & 1) * STAGE, lane, wm, wn, acc);
        __syncthreads();
    }

#pragma unroll
    for (int mt = 0; mt < 2; mt++) {
        int r0 = m0 + wm * 32 + mt * 16 + (lane >> 2);
#pragma unroll
        for (int nt = 0; nt < 8; nt++) {
            int cc = n0 + wn * 64 + nt * 8 + (lane & 3) * 2;
            *(__half2*)&g_h2[(size_t)r0 * N1 + cc] =
                __floats2half2_rn(acc[mt][nt][0], acc[mt][nt][1]);
            *(__half2*)&g_h2[(size_t)(r0 + 8) * N1 + cc] =
                __floats2half2_rn(acc[mt][nt][2], acc[mt][nt][3]);
        }
    }

    // per-CTA column stats over this CTA's 128 rows (exact fp32 acc)
    float s[8][2], q[8][2];
#pragma unroll
    for (int nt = 0; nt < 8; nt++)
#pragma unroll
        for (int p = 0; p < 2; p++) {
            float a0 = acc[0][nt][p], a1 = acc[0][nt][2 + p];
            float a2 = acc[1][nt][p], a3 = acc[1][nt][2 + p];
            s[nt][p] = a0 + a1 + a2 + a3;
            q[nt][p] = a0 * a0 + a1 * a1 + a2 * a2 + a3 * a3;
        }
#pragma unroll
    for (int off = 4; off < 32; off <<= 1)
#pragma unroll
        for (int nt = 0; nt < 8; nt++)
#pragma unroll
            for (int p = 0; p < 2; p++) {
                s[nt][p] += __shfl_xor_sync(0xffffffffu, s[nt][p], off);
                q[nt][p] += __shfl_xor_sync(0xffffffffu, q[nt][p], off);
            }
    float* red = (float*)smem;
    if (lane < 4) {
#pragma unroll
        for (int nt = 0; nt < 8; nt++)
#pragma unroll
            for (int p = 0; p < 2; p++) {
                int cl = wn * 64 + nt * 8 + lane * 2 + p;
                red[(wm * 128 + cl) * 2 + 0] = s[nt][p];
                red[(wm * 128 + cl) * 2 + 1] = q[nt][p];
            }
    }
    __syncthreads();
    if (threadIdx.x < 128) {
        int cl = threadIdx.x;
        float S = red[cl * 2]           + red[(128 + cl) * 2] +
                  red[(256 + cl) * 2]   + red[(384 + cl) * 2];
        float Q = red[cl * 2 + 1]         + red[(128 + cl) * 2 + 1] +
                  red[(256 + cl) * 2 + 1] + red[(384 + cl) * 2 + 1];
        g_part[blockIdx.y][2 * (n0 + cl)]     = S;
        g_part[blockIdx.y][2 * (n0 + cl) + 1] = Q;
    }
}

// ---------------------------------------------------------------------------
// GEMM2: cand = LN(h) @ w2t^T (LN fused in A-loader);
// epilogue: +b2, fp32 residual, Benes scatter.
__global__ __launch_bounds__(256, 2) void gemm2_mma(int stage, int dir, int cur,
                                                    const float* __restrict__ b2,
                                                    float* __restrict__ dext) {
    extern __shared__ char smem[];
    uint32_t sb = smem_u32(smem);
    int m0 = blockIdx.y * 128, n0 = blockIdx.x * 128;

    // preload stats cache (16KB)
    float* ssm = (float*)(smem + 2 * STAGE);
#pragma unroll
    for (int i = 0; i < 4; i++)
        ((float4*)ssm)[threadIdx.x + i * 256] = ((const float4*)g_stats)[threadIdx.x + i * 256];
    __syncthreads();

    float acc[2][8][4];
#pragma unroll
    for (int i = 0; i < 2; i++)
#pragma unroll
        for (int j = 0; j < 8; j++)
#pragma unroll
            for (int q = 0; q < 4; q++) acc[i][j][q] = 0.f;

    const int lane = threadIdx.x & 31, wid = threadIdx.x >> 5;
    const int wm = wid & 3, wn = wid >> 2;
    const __half* A = g_h2;
    const __half* B = g_w2t[stage];

    load_stage_ln(sb, smem, 0, 0, A, B, m0, n0, ssm);
    for (int ck = 0; ck < (K2 >> 6); ck++) {
        if (ck + 1 < (K2 >> 6)) {
            load_stage_ln(sb, smem, (ck + 1) & 1, ck + 1, A, B, m0, n0, ssm);
            asm volatile("cp.async.wait_group 1;" ::: "memory");
        } else {
            asm volatile("cp.async.wait_group 0;" ::: "memory");
        }
        __syncthreads();
        compute_chunk(sb + (ck & 1) * STAGE, lane, wm, wn, acc);
        __syncthreads();
    }

    const float* y = g_y32[cur];
    float* oy = g_y32[cur ^ 1];
    __half* o16 = g_y16[cur ^ 1];

#pragma unroll
    for (int mt = 0; mt < 2; mt++) {
        int rbase = m0 + wm * 32 + mt * 16 + (lane >> 2);
#pragma unroll
        for (int nt = 0; nt < 8; nt++) {
            int n = n0 + wn * 64 + nt * 8 + (lane & 3) * 2;
            int c = n & (NU - 1);
            int b = n >> 9;
            float2 bias = *(const float2*)&b2[n];
            float sig0 = g_sig[stage * NU + c];
            float sig1 = g_sig[stage * NU + c + 1];
#pragma unroll
            for (int hf = 0; hf < 2; hf++) {
                int r = rbase + hf * 8;
                int rowY = 2 * r + b;
                float cand0 = acc[mt][nt][hf * 2 + 0] + bias.x;
                float cand1 = acc[mt][nt][hf * 2 + 1] + bias.y;
                float2 yv = *(const float2*)&y[(size_t)rowY * NU + c];
                float v0 = sig0 * yv.x + cand0 * CW_F;
                float v1 = sig1 * yv.y + cand1 * CW_F;
                int dst;
                if (dir == 0)      dst = (rowY < M_) ? (2 * rowY) : (2 * rowY - L + 1);
                else if (dir == 1) dst = (rowY & 1) ? (M_ + (rowY >> 1)) : (rowY >> 1);
                else               dst = rowY;
                if (dext) {
                    *(float2*)&dext[(size_t)dst * NU + c] = make_float2(v0, v1);
                } else {
                    *(float2*)&oy[(size_t)dst * NU + c] = make_float2(v0, v1);
                    *(__half2*)&o16[(size_t)dst * NU + c] =
                        __halves2half2(__float2half_rn(v0), __float2half_rn(v1));
                }
            }
        }
    }
}

// ---------------------------------------------------------------------------
extern "C" void kernel_launch(void* const* d_in, const int* in_sizes, int n_in,
                              void* d_out, int out_size) {
    const float* x = (const float*)d_in[0];
    const float* rs[3] = {(const float*)d_in[1], (const float*)d_in[5], (const float*)d_in[9]};
    const float* w1[3] = {(const float*)d_in[2], (const float*)d_in[6], (const float*)d_in[10]};
    const float* w2[3] = {(const float*)d_in[3], (const float*)d_in[7], (const float*)d_in[11]};
    const float* b2[3] = {(const float*)d_in[4], (const float*)d_in[8], (const float*)d_in[12]};
    float* out = (float*)d_out;

    cudaFuncSetAttribute(gemm1_mma, cudaFuncAttributeMaxDynamicSharedMemorySize, SMEM_DYN);
    cudaFuncSetAttribute(gemm2_mma, cudaFuncAttributeMaxDynamicSharedMemorySize, SMEM_DYN);

    copy_x_kernel<<<(L * NU) / 256 + 1, 256>>>(x, rs[0], rs[1], rs[2]);
    transpose_half_all<<<dim3(64, 64, 6), dim3(32, 8)>>>(w1[0], w2[0], w1[1], w2[1], w1[2], w2[2]);

    dim3 g1(N1 / 128, M_ / 128);   // (16, 32)
    dim3 g2(N2 / 128, M_ / 128);   // (8, 32)

    int cur = 0;
    for (int step = 0; step < 25; step++) {
        int stage = (step < 12) ? 0 : (step < 24) ? 1 : 2;
        int dir = stage;
        gemm1_mma<<<g1, 256, SMEM_DYN>>>(cur, stage);
        stats_final_kernel<<<8, 256>>>();
        gemm2_mma<<<g2, 256, SMEM_DYN>>>(stage, dir, cur, b2[stage],
                                         (step == 24) ? out : nullptr);
        cur ^= 1;
    }
}

// round 12
// speedup vs baseline: 1.0456x; 1.0328x over previous
#include <cuda_runtime.h>
#include <cuda_fp16.h>
#include <cstdint>

// ---------------------------------------------------------------------------
// BenesBlock via mma.sync (HMMA), single-pass fp16 GEMMs.
// Residual exact fp32 (g_y32); fp16 shadow feeds GEMM1. h stored fp16 raw.
// LN + leaky-relu fused into gemm2's A *fragments* (post-ldmatrix, in-register
// half2 affine) -> A loads stay cp.async; no prep2 kernel.
// Per step: gemm1 (+fused stats partials) -> stats_final (tiny) -> gemm2.
// ---------------------------------------------------------------------------

#define L    8192
#define NU   512
#define M_   4096
#define K1   1024
#define N1   2048
#define K2   2048
#define N2   1024
#define CW_F 0.10897247358851683f
#define EPS_F 1e-6f

#define STAGE 32768                       // A16K | B16K
#define SMEM_DYN (2 * STAGE + 8192)       // + LN coeff cache (gemm2)

// ---------------------------------------------------------------------------
__device__ __align__(16) float  g_y32[2][L * NU];         // exact residual
__device__ __align__(16) __half g_y16[2][L * NU];         // GEMM1 A operand
__device__ __align__(16) __half g_h2[M_ * N1];            // raw h (fp16)
__device__ __align__(16) __half g_w1t[3][N1 * K1];        // [stage][N,K] fp16
__device__ __align__(16) __half g_w2t[3][N2 * K2];
__device__ float g_part[32][2 * N1];
__device__ __align__(16) __half g_lns[N1];                // rstd (fp16)
__device__ __align__(16) __half g_lnb[N1];                // -mean*rstd (fp16)
__device__ float g_sig[3 * NU];

// ---------------------------------------------------------------------------
__device__ __forceinline__ uint32_t smem_u32(const void* p) {
    uint32_t a;
    asm("{ .reg .u64 t; cvta.to.shared.u64 t, %1; cvt.u32.u64 %0, t; }" : "=r"(a) : "l"(p));
    return a;
}
__device__ __forceinline__ uint32_t sw128(uint32_t off) { return off ^ ((off >> 3) & 0x70); }

#define CP16(s, g) asm volatile("cp.async.cg.shared.global [%0], [%1], 16;" :: "r"(s), "l"(g))
#define CP_COMMIT() asm volatile("cp.async.commit_group;" ::: "memory")

#define LDSM4(r0, r1, r2, r3, addr)                                              \
    asm volatile("ldmatrix.sync.aligned.m8n8.x4.shared.b16 {%0,%1,%2,%3}, [%4];" \
                 : "=r"(r0), "=r"(r1), "=r"(r2), "=r"(r3) : "r"(addr))

#define MMA(acc, a, b0, b1)                                                      \
    asm volatile("mma.sync.aligned.m16n8k16.row.col.f32.f16.f16.f32 "            \
                 "{%0,%1,%2,%3}, {%4,%5,%6,%7}, {%8,%9}, {%0,%1,%2,%3};"         \
                 : "+f"((acc)[0]), "+f"((acc)[1]), "+f"((acc)[2]), "+f"((acc)[3])\
                 : "r"((a)[0]), "r"((a)[1]), "r"((a)[2]), "r"((a)[3]),           \
                   "r"(b0), "r"(b1))

// ---------------------------------------------------------------------------
__global__ void copy_x_kernel(const float* __restrict__ x,
                              const float* __restrict__ rs_f,
                              const float* __restrict__ rs_r,
                              const float* __restrict__ rs_m) {
    if (blockIdx.x == (L * NU) / 256) {
        for (int i = threadIdx.x; i < 3 * NU; i += 256) {
            const float* src = (i < NU) ? rs_f : (i < 2 * NU) ? rs_r : rs_m;
            float v = src[i & (NU - 1)];
            g_sig[i] = 1.0f / (1.0f + expf(-v));
        }
        return;
    }
    int i = blockIdx.x * 256 + threadIdx.x;
    float v = x[i];
    g_y32[0][i] = v;
    g_y16[0][i] = __float2half_rn(v);
}

// All 6 weight transposes in one launch. z: stage = z>>1, which = z&1.
__global__ void transpose_half_all(const float* __restrict__ w1f, const float* __restrict__ w2f,
                                   const float* __restrict__ w1r, const float* __restrict__ w2r,
                                   const float* __restrict__ w1m, const float* __restrict__ w2m) {
    __shared__ float t[32][33];
    int stage = blockIdx.z >> 1;
    int which = blockIdx.z & 1;
    int R = which ? K2 : K1;
    int C = which ? N2 : N1;
    if ((int)blockIdx.x * 32 >= C || (int)blockIdx.y * 32 >= R) return;
    const float* w = which ? (stage == 0 ? w2f : stage == 1 ? w2r : w2m)
                           : (stage == 0 ? w1f : stage == 1 ? w1r : w1m);
    __half* o = which ? g_w2t[stage] : g_w1t[stage];
    int c0 = blockIdx.x * 32, r0 = blockIdx.y * 32;
    for (int j = threadIdx.y; j < 32; j += 8)
        t[j][threadIdx.x] = w[(size_t)(r0 + j) * C + c0 + threadIdx.x];
    __syncthreads();
    for (int j = threadIdx.y; j < 32; j += 8) {
        float v = t[threadIdx.x][j];
        o[(size_t)(c0 + j) * R + r0 + threadIdx.x] = __float2half_rn(v);
    }
}

// ---------------------------------------------------------------------------
// Reduce partials -> fp16 LN coefficients: lns = rstd, lnb = -mean*rstd.
__global__ void stats_final_kernel() {     // grid 8, block 256
    int c = blockIdx.x * 256 + threadIdx.x;
    float s = 0.f, q = 0.f;
#pragma unroll
    for (int rg = 0; rg < 32; rg++) { s += g_part[rg][2 * c]; q += g_part[rg][2 * c + 1]; }
    float mean = s * (1.0f / M_);
    float var = q * (1.0f / M_) - mean * mean;
    float rstd = rsqrtf(var + EPS_F);
    g_lns[c] = __float2half_rn(rstd);
    g_lnb[c] = __float2half_rn(-mean * rstd);
}

// ---------------------------------------------------------------------------
// Stage loader: A and B both via cp.async (8 per thread).
__device__ __forceinline__ void load_stage(uint32_t sb, int s, int ck,
                                           const __half* A, const __half* B,
                                           int Kt, int m0, int n0) {
    int tid = threadIdx.x;
    int r = tid >> 1;
    int c0 = (tid & 1) * 4;
    uint32_t base = sb + s * STAGE;
    size_t rs = (size_t)Kt * 2;
    size_t kb = (size_t)ck * 128;
    const char* pA = (const char*)A + (size_t)(m0 + r) * rs + kb;
    const char* pB = (const char*)B + (size_t)(n0 + r) * rs + kb;
#pragma unroll
    for (int c = 0; c < 4; c++) {
        int ch = c0 + c;
        uint32_t so = sw128((uint32_t)(r * 128 + ch * 16));
        CP16(base + so,         pA + ch * 16);
        CP16(base + 16384 + so, pB + ch * 16);
    }
    CP_COMMIT();
}

__device__ __forceinline__ void compute_chunk(uint32_t base, int lane, int wm, int wn,
                                              float acc[2][8][4]) {
#pragma unroll
    for (int k16 = 0; k16 < 4; k16++) {
        uint32_t koff = k16 * 32 + (lane >> 4) * 16;
        uint32_t ah[2][4];
#pragma unroll
        for (int mt = 0; mt < 2; mt++) {
            int row = wm * 32 + mt * 16 + (lane & 15);
            uint32_t off = sw128((uint32_t)(row * 128) + koff);
            LDSM4(ah[mt][0], ah[mt][1], ah[mt][2], ah[mt][3], base + off);
        }
        uint32_t bh[8][2];
#pragma unroll
        for (int g = 0; g < 4; g++) {
            int row = wn * 64 + g * 16 + (lane & 15);
            uint32_t off = sw128((uint32_t)(row * 128) + koff);
            uint32_t q0, q1, q2, q3;
            LDSM4(q0, q1, q2, q3, base + 16384 + off);
            bh[2 * g][0] = q0; bh[2 * g][1] = q2;
            bh[2 * g + 1][0] = q1; bh[2 * g + 1][1] = q3;
        }
#pragma unroll
        for (int mt = 0; mt < 2; mt++)
#pragma unroll
            for (int nt = 0; nt < 8; nt++)
                MMA(acc[mt][nt], ah[mt], bh[nt][0], bh[nt][1]);
    }
}

// gemm2 chunk: LN+lrelu applied to A fragments in registers.
// A-fragment k-coords: regs 0,1 -> k = k16*16 + (lane&3)*2 + {0,1};
// regs 2,3 -> +8. Coeffs as half2 from smem cache (per-chunk base s2/b2).
__device__ __forceinline__ void compute_chunk_ln(uint32_t base, int lane, int wm, int wn,
                                                 float acc[2][8][4],
                                                 const __half2* s2, const __half2* b2) {
    const __half2 c02 = __float2half2_rn(0.2f);
#pragma unroll
    for (int k16 = 0; k16 < 4; k16++) {
        uint32_t koff = k16 * 32 + (lane >> 4) * 16;
        int si = k16 * 8 + (lane & 3);
        __half2 sA = s2[si], bA = b2[si];
        __half2 sB = s2[si + 4], bB = b2[si + 4];
        uint32_t ah[2][4];
#pragma unroll
        for (int mt = 0; mt < 2; mt++) {
            int row = wm * 32 + mt * 16 + (lane & 15);
            uint32_t off = sw128((uint32_t)(row * 128) + koff);
            LDSM4(ah[mt][0], ah[mt][1], ah[mt][2], ah[mt][3], base + off);
#pragma unroll
            for (int j = 0; j < 4; j++) {
                __half2 h = *(__half2*)&ah[mt][j];
                __half2 t = __hfma2(h, (j < 2) ? sA : sB, (j < 2) ? bA : bB);
                t = __hmax2(t, __hmul2(t, c02));        // leaky relu 0.2
                ah[mt][j] = *(uint32_t*)&t;
            }
        }
        uint32_t bh[8][2];
#pragma unroll
        for (int g = 0; g < 4; g++) {
            int row = wn * 64 + g * 16 + (lane & 15);
            uint32_t off = sw128((uint32_t)(row * 128) + koff);
            uint32_t q0, q1, q2, q3;
            LDSM4(q0, q1, q2, q3, base + 16384 + off);
            bh[2 * g][0] = q0; bh[2 * g][1] = q2;
            bh[2 * g + 1][0] = q1; bh[2 * g + 1][1] = q3;
        }
#pragma unroll
        for (int mt = 0; mt < 2; mt++)
#pragma unroll
            for (int nt = 0; nt < 8; nt++)
                MMA(acc[mt][nt], ah[mt], bh[nt][0], bh[nt][1]);
    }
}

// ---------------------------------------------------------------------------
// GEMM1: h(fp16 raw) = y16 @ w1t^T + fused per-CTA stats partials.
__global__ __launch_bounds__(256, 2) void gemm1_mma(int cur, int stage) {
    extern __shared__ char smem[];
    uint32_t sb = smem_u32(smem);
    int m0 = blockIdx.y * 128, n0 = blockIdx.x * 128;
    float acc[2][8][4];
#pragma unroll
    for (int i = 0; i < 2; i++)
#pragma unroll
        for (int j = 0; j < 8; j++)
#pragma unroll
            for (int q = 0; q < 4; q++) acc[i][j][q] = 0.f;

    const int lane = threadIdx.x & 31, wid = threadIdx.x >> 5;
    const int wm = wid & 3, wn = wid >> 2;
    const __half* A = g_y16[cur];
    const __half* B = g_w1t[stage];

    load_stage(sb, 0, 0, A, B, K1, m0, n0);
    for (int ck = 0; ck < (K1 >> 6); ck++) {
        if (ck + 1 < (K1 >> 6)) {
            load_stage(sb, (ck + 1) & 1, ck + 1, A, B, K1, m0, n0);
            asm volatile("cp.async.wait_group 1;" ::: "memory");
        } else {
            asm volatile("cp.async.wait_group 0;" ::: "memory");
        }
        __syncthreads();
        compute_chunk(sb + (ck & 1) * STAGE, lane, wm, wn, acc);
        __syncthreads();
    }

#pragma unroll
    for (int mt = 0; mt < 2; mt++) {
        int r0 = m0 + wm * 32 + mt * 16 + (lane >> 2);
#pragma unroll
        for (int nt = 0; nt < 8; nt++) {
            int cc = n0 + wn * 64 + nt * 8 + (lane & 3) * 2;
            *(__half2*)&g_h2[(size_t)r0 * N1 + cc] =
                __floats2half2_rn(acc[mt][nt][0], acc[mt][nt][1]);
            *(__half2*)&g_h2[(size_t)(r0 + 8) * N1 + cc] =
                __floats2half2_rn(acc[mt][nt][2], acc[mt][nt][3]);
        }
    }

    // per-CTA column stats over this CTA's 128 rows (exact fp32 acc)
    float s[8][2], q[8][2];
#pragma unroll
    for (int nt = 0; nt < 8; nt++)
#pragma unroll
        for (int p = 0; p < 2; p++) {
            float a0 = acc[0][nt][p], a1 = acc[0][nt][2 + p];
            float a2 = acc[1][nt][p], a3 = acc[1][nt][2 + p];
            s[nt][p] = a0 + a1 + a2 + a3;
            q[nt][p] = a0 * a0 + a1 * a1 + a2 * a2 + a3 * a3;
        }
#pragma unroll
    for (int off = 4; off < 32; off <<= 1)
#pragma unroll
        for (int nt = 0; nt < 8; nt++)
#pragma unroll
            for (int p = 0; p < 2; p++) {
                s[nt][p] += __shfl_xor_sync(0xffffffffu, s[nt][p], off);
                q[nt][p] += __shfl_xor_sync(0xffffffffu, q[nt][p], off);
            }
    float* red = (float*)smem;
    if (lane < 4) {
#pragma unroll
        for (int nt = 0; nt < 8; nt++)
#pragma unroll
            for (int p = 0; p < 2; p++) {
                int cl = wn * 64 + nt * 8 + lane * 2 + p;
                red[(wm * 128 + cl) * 2 + 0] = s[nt][p];
                red[(wm * 128 + cl) * 2 + 1] = q[nt][p];
            }
    }
    __syncthreads();
    if (threadIdx.x < 128) {
        int cl = threadIdx.x;
        float S = red[cl * 2]           + red[(128 + cl) * 2] +
                  red[(256 + cl) * 2]   + red[(384 + cl) * 2];
        float Q = red[cl * 2 + 1]         + red[(128 + cl) * 2 + 1] +
                  red[(256 + cl) * 2 + 1] + red[(384 + cl) * 2 + 1];
        g_part[blockIdx.y][2 * (n0 + cl)]     = S;
        g_part[blockIdx.y][2 * (n0 + cl) + 1] = Q;
    }
}

// ---------------------------------------------------------------------------
// GEMM2: cand = lrelu(LN(h)) @ w2t^T with LN fused post-ldmatrix;
// epilogue: +b2, fp32 residual, Benes scatter.
__global__ __launch_bounds__(256, 2) void gemm2_mma(int stage, int dir, int cur,
                                                    const float* __restrict__ b2,
                                                    float* __restrict__ dext) {
    extern __shared__ char smem[];
    uint32_t sb = smem_u32(smem);
    int m0 = blockIdx.y * 128, n0 = blockIdx.x * 128;

    // preload LN coeff cache (4KB + 4KB)
    __half* lns_c = (__half*)(smem + 2 * STAGE);
    __half* lnb_c = (__half*)(smem + 2 * STAGE + 4096);
    ((uint4*)lns_c)[threadIdx.x] = ((const uint4*)g_lns)[threadIdx.x];
    ((uint4*)lnb_c)[threadIdx.x] = ((const uint4*)g_lnb)[threadIdx.x];
    __syncthreads();

    float acc[2][8][4];
#pragma unroll
    for (int i = 0; i < 2; i++)
#pragma unroll
        for (int j = 0; j < 8; j++)
#pragma unroll
            for (int q = 0; q < 4; q++) acc[i][j][q] = 0.f;

    const int lane = threadIdx.x & 31, wid = threadIdx.x >> 5;
    const int wm = wid & 3, wn = wid >> 2;
    const __half* A = g_h2;
    const __half* B = g_w2t[stage];

    load_stage(sb, 0, 0, A, B, K2, m0, n0);
    for (int ck = 0; ck < (K2 >> 6); ck++) {
        if (ck + 1 < (K2 >> 6)) {
            load_stage(sb, (ck + 1) & 1, ck + 1, A, B, K2, m0, n0);
            asm volatile("cp.async.wait_group 1;" ::: "memory");
        } else {
            asm volatile("cp.async.wait_group 0;" ::: "memory");
        }
        __syncthreads();
        compute_chunk_ln(sb + (ck & 1) * STAGE, lane, wm, wn, acc,
                         (const __half2*)lns_c + ck * 32,
                         (const __half2*)lnb_c + ck * 32);
        __syncthreads();
    }

    const float* y = g_y32[cur];
    float* oy = g_y32[cur ^ 1];
    __half* o16 = g_y16[cur ^ 1];

#pragma unroll
    for (int mt = 0; mt < 2; mt++) {
        int rbase = m0 + wm * 32 + mt * 16 + (lane >> 2);
#pragma unroll
        for (int nt = 0; nt < 8; nt++) {
            int n = n0 + wn * 64 + nt * 8 + (lane & 3) * 2;
            int c = n & (NU - 1);
            int b = n >> 9;
            float2 bias = *(const float2*)&b2[n];
            float sig0 = g_sig[stage * NU + c];
            float sig1 = g_sig[stage * NU + c + 1];
#pragma unroll
            for (int hf = 0; hf < 2; hf++) {
                int r = rbase + hf * 8;
                int rowY = 2 * r + b;
                float cand0 = acc[mt][nt][hf * 2 + 0] + bias.x;
                float cand1 = acc[mt][nt][hf * 2 + 1] + bias.y;
                float2 yv = *(const float2*)&y[(size_t)rowY * NU + c];
                float v0 = sig0 * yv.x + cand0 * CW_F;
                float v1 = sig1 * yv.y + cand1 * CW_F;
                int dst;
                if (dir == 0)      dst = (rowY < M_) ? (2 * rowY) : (2 * rowY - L + 1);
                else if (dir == 1) dst = (rowY & 1) ? (M_ + (rowY >> 1)) : (rowY >> 1);
                else               dst = rowY;
                if (dext) {
                    *(float2*)&dext[(size_t)dst * NU + c] = make_float2(v0, v1);
                } else {
                    *(float2*)&oy[(size_t)dst * NU + c] = make_float2(v0, v1);
                    *(__half2*)&o16[(size_t)dst * NU + c] =
                        __halves2half2(__float2half_rn(v0), __float2half_rn(v1));
                }
            }
        }
    }
}

// ---------------------------------------------------------------------------
extern "C" void kernel_launch(void* const* d_in, const int* in_sizes, int n_in,
                              void* d_out, int out_size) {
    const float* x = (const float*)d_in[0];
    const float* rs[3] = {(const float*)d_in[1], (const float*)d_in[5], (const float*)d_in[9]};
    const float* w1[3] = {(const float*)d_in[2], (const float*)d_in[6], (const float*)d_in[10]};
    const float* w2[3] = {(const float*)d_in[3], (const float*)d_in[7], (const float*)d_in[11]};
    const float* b2[3] = {(const float*)d_in[4], (const float*)d_in[8], (const float*)d_in[12]};
    float* out = (float*)d_out;

    cudaFuncSetAttribute(gemm1_mma, cudaFuncAttributeMaxDynamicSharedMemorySize, SMEM_DYN);
    cudaFuncSetAttribute(gemm2_mma, cudaFuncAttributeMaxDynamicSharedMemorySize, SMEM_DYN);

    copy_x_kernel<<<(L * NU) / 256 + 1, 256>>>(x, rs[0], rs[1], rs[2]);
    transpose_half_all<<<dim3(64, 64, 6), dim3(32, 8)>>>(w1[0], w2[0], w1[1], w2[1], w1[2], w2[2]);

    dim3 g1(N1 / 128, M_ / 128);   // (16, 32)
    dim3 g2(N2 / 128, M_ / 128);   // (8, 32)

    int cur = 0;
    for (int step = 0; step < 25; step++) {
        int stage = (step < 12) ? 0 : (step < 24) ? 1 : 2;
        int dir = stage;
        gemm1_mma<<<g1, 256, SMEM_DYN>>>(cur, stage);
        stats_final_kernel<<<8, 256>>>();
        gemm2_mma<<<g2, 256, SMEM_DYN>>>(stage, dir, cur, b2[stage],
                                         (step == 24) ? out : nullptr);
        cur ^= 1;
    }
}